// round 14
// baseline (speedup 1.0000x reference)
#include <cuda_runtime.h>
#include <cuda_bf16.h>
#include <math.h>
#include <stdint.h>

#define TGT 2048
#define BSZ 2
#define EMB 1024
#define NH 16
#define HD 64
#define ROWS (TGT*BSZ)              // 4096
#define BH (BSZ*NH)                 // 32
#define ATTN_N (ROWS*EMB)           // 4194304
#define W_ELEMS (134217728LL)       // 32*2048*2048
#define NEGMAX (-3.4028234663852886e38f)
#define NTILE 16                    // 2048/128 key tiles
#define KD 1024
#define NQ (ROWS*EMB)               // 4194304
#define NW (EMB*EMB)                // 1048576

// ---------------- scratch (static device memory; no allocations) -------------
__device__ float g_wfallback[134217728];
__device__ unsigned char g_mask[BSZ*TGT];
__device__ float g_tmax[BH*NTILE*TGT];
__device__ float g_tsum[BH*NTILE*TGT];
__device__ float g_rmax[BH*TGT];
__device__ float g_rinv[BH*TGT];

// split-bf16 operands
__device__ __nv_bfloat16 g_ah[ROWS*EMB], g_al[ROWS*EMB];          // input query hi/lo
__device__ __nv_bfloat16 g_ch[ROWS*EMB], g_cl[ROWS*EMB];          // ctx hi/lo
__device__ __nv_bfloat16 g_qh[ROWS*EMB], g_ql[ROWS*EMB];          // projected q hi/lo
__device__ __nv_bfloat16 g_kh[ROWS*EMB], g_kl[ROWS*EMB];          // projected k hi/lo
__device__ __nv_bfloat16 g_vh[ROWS*EMB], g_vl[ROWS*EMB];          // projected v hi/lo
__device__ __nv_bfloat16 g_qwh[EMB*EMB], g_qwl[EMB*EMB];
__device__ __nv_bfloat16 g_kwh[EMB*EMB], g_kwl[EMB*EMB];
__device__ __nv_bfloat16 g_vwh[EMB*EMB], g_vwl[EMB*EMB];
__device__ __nv_bfloat16 g_owh[EMB*EMB], g_owl[EMB*EMB];

// ---------------- helpers ----------------------------------------------------
__device__ __forceinline__ uint32_t smem_u32(const void* p) {
    uint32_t a;
    asm("{ .reg .u64 t; cvta.to.shared.u64 t, %1; cvt.u32.u64 %0, t; }" : "=r"(a) : "l"(p));
    return a;
}
__device__ __forceinline__ void ldmx4(uint32_t& r0, uint32_t& r1, uint32_t& r2, uint32_t& r3, uint32_t addr) {
    asm volatile("ldmatrix.sync.aligned.m8n8.x4.shared.b16 {%0,%1,%2,%3}, [%4];"
                 : "=r"(r0), "=r"(r1), "=r"(r2), "=r"(r3) : "r"(addr));
}
__device__ __forceinline__ void ldmx4t(uint32_t& r0, uint32_t& r1, uint32_t& r2, uint32_t& r3, uint32_t addr) {
    asm volatile("ldmatrix.sync.aligned.m8n8.x4.trans.shared.b16 {%0,%1,%2,%3}, [%4];"
                 : "=r"(r0), "=r"(r1), "=r"(r2), "=r"(r3) : "r"(addr));
}
__device__ __forceinline__ void mma_bf16(float* d, const uint32_t* a, const uint32_t* b) {
    asm volatile("mma.sync.aligned.m16n8k16.row.col.f32.bf16.bf16.f32 "
                 "{%0,%1,%2,%3}, {%4,%5,%6,%7}, {%8,%9}, {%0,%1,%2,%3};"
                 : "+f"(d[0]), "+f"(d[1]), "+f"(d[2]), "+f"(d[3])
                 : "r"(a[0]), "r"(a[1]), "r"(a[2]), "r"(a[3]), "r"(b[0]), "r"(b[1]));
}
__device__ __forceinline__ void split1(float x, __nv_bfloat16& h, __nv_bfloat16& l) {
    h = __float2bfloat16_rn(x);
    l = __float2bfloat16_rn(x - __bfloat162float(h));
}
__device__ __forceinline__ void split2(float x, float y, uint32_t& hi, uint32_t& lo) {
    __nv_bfloat162 h, l;
    split1(x, h.x, l.x);
    split1(y, h.y, l.y);
    hi = *(uint32_t*)&h;
    lo = *(uint32_t*)&l;
}

// ---------------- fused fp32 -> (hi, lo) bf16 split for all 5 tensors --------
__global__ __launch_bounds__(256) void split_all(
    const float* __restrict__ query, const float* __restrict__ qw,
    const float* __restrict__ kw, const float* __restrict__ vw,
    const float* __restrict__ ow)
{
    size_t i = ((size_t)blockIdx.x * 256 + threadIdx.x) * 4;
    const float* src;
    __nv_bfloat16 *hi, *lo;
    size_t off;
    if (i < NQ)              { src = query; hi = g_ah;  lo = g_al;  off = i; }
    else if (i < NQ + NW)    { src = qw;    hi = g_qwh; lo = g_qwl; off = i - NQ; }
    else if (i < NQ + 2*NW)  { src = kw;    hi = g_kwh; lo = g_kwl; off = i - NQ - NW; }
    else if (i < NQ + 3*NW)  { src = vw;    hi = g_vwh; lo = g_vwl; off = i - NQ - 2*NW; }
    else                     { src = ow;    hi = g_owh; lo = g_owl; off = i - NQ - 3*NW; }
    float4 x = *(const float4*)(src + off);
    __nv_bfloat162 hh0, hh1, ll0, ll1;
    split1(x.x, hh0.x, ll0.x); split1(x.y, hh0.y, ll0.y);
    split1(x.z, hh1.x, ll1.x); split1(x.w, hh1.y, ll1.y);
    *(__nv_bfloat162*)(hi + off) = hh0; *(__nv_bfloat162*)(hi + off + 2) = hh1;
    *(__nv_bfloat162*)(lo + off) = ll0; *(__nv_bfloat162*)(lo + off + 2) = ll1;
}

// ---------------- split-bf16 HMMA NT GEMM core --------------------------------
#define SSTR 40

template<bool EMIT_F32>
__device__ __forceinline__ void hgemm_body(
    const __nv_bfloat16* __restrict__ Ah, const __nv_bfloat16* __restrict__ Al,
    const __nv_bfloat16* __restrict__ Bh, const __nv_bfloat16* __restrict__ Bl,
    const float* __restrict__ bias, float* __restrict__ Cf,
    __nv_bfloat16* __restrict__ Chi, __nv_bfloat16* __restrict__ Clo, float scale,
    __nv_bfloat16* sA0, __nv_bfloat16* sA1, __nv_bfloat16* sB0, __nv_bfloat16* sB1)
{
    int tid = threadIdx.x;
    int warp = tid >> 5, lane = tid & 31;
    int wm = warp & 1, wn = warp >> 1;
    int m0 = blockIdx.y * 128, n0 = blockIdx.x * 128;

    uint32_t sAh_u = smem_u32(sA0), sAl_u = smem_u32(sA1);
    uint32_t sBh_u = smem_u32(sB0), sBl_u = smem_u32(sB1);

    float acc[4][4][4];
#pragma unroll
    for (int i = 0; i < 4; i++)
#pragma unroll
        for (int j = 0; j < 4; j++)
#pragma unroll
            for (int q = 0; q < 4; q++) acc[i][j][q] = 0.f;

    int e0 = tid, e1 = tid + 256;
    int r0 = e0 >> 2, c0 = (e0 & 3) * 8;
    int r1 = e1 >> 2, c1 = (e1 & 3) * 8;

    int arow = lane & 15;
    int acolh = (lane >> 4) * 8;
    int brow = (lane & 7) + ((lane >> 4) & 1) * 8;
    int bcolh = ((lane >> 3) & 1) * 8;

    for (int kt = 0; kt < KD; kt += 32) {
        __syncthreads();
        {
            const __nv_bfloat16* a_h = Ah + (size_t)m0 * KD + kt;
            const __nv_bfloat16* a_l = Al + (size_t)m0 * KD + kt;
            const __nv_bfloat16* b_h = Bh + (size_t)n0 * KD + kt;
            const __nv_bfloat16* b_l = Bl + (size_t)n0 * KD + kt;
            *(uint4*)&sA0[r0 * SSTR + c0] = *(const uint4*)(a_h + (size_t)r0 * KD + c0);
            *(uint4*)&sA0[r1 * SSTR + c1] = *(const uint4*)(a_h + (size_t)r1 * KD + c1);
            *(uint4*)&sA1[r0 * SSTR + c0] = *(const uint4*)(a_l + (size_t)r0 * KD + c0);
            *(uint4*)&sA1[r1 * SSTR + c1] = *(const uint4*)(a_l + (size_t)r1 * KD + c1);
            *(uint4*)&sB0[r0 * SSTR + c0] = *(const uint4*)(b_h + (size_t)r0 * KD + c0);
            *(uint4*)&sB0[r1 * SSTR + c1] = *(const uint4*)(b_h + (size_t)r1 * KD + c1);
            *(uint4*)&sB1[r0 * SSTR + c0] = *(const uint4*)(b_l + (size_t)r0 * KD + c0);
            *(uint4*)&sB1[r1 * SSTR + c1] = *(const uint4*)(b_l + (size_t)r1 * KD + c1);
        }
        __syncthreads();

#pragma unroll
        for (int ks = 0; ks < 32; ks += 16) {
            uint32_t ahf[4][4], alf[4][4];
#pragma unroll
            for (int mt = 0; mt < 4; mt++) {
                int r = wm * 64 + mt * 16 + arow;
                uint32_t off = (uint32_t)(r * SSTR + ks + acolh) * 2;
                ldmx4(ahf[mt][0], ahf[mt][1], ahf[mt][2], ahf[mt][3], sAh_u + off);
                ldmx4(alf[mt][0], alf[mt][1], alf[mt][2], alf[mt][3], sAl_u + off);
            }
            uint32_t bhf[4][2], blf[4][2];
#pragma unroll
            for (int ntp = 0; ntp < 2; ntp++) {
                int nb = wn * 32 + ntp * 16;
                uint32_t off = (uint32_t)((nb + brow) * SSTR + ks + bcolh) * 2;
                ldmx4(bhf[2*ntp][0], bhf[2*ntp][1], bhf[2*ntp+1][0], bhf[2*ntp+1][1], sBh_u + off);
                ldmx4(blf[2*ntp][0], blf[2*ntp][1], blf[2*ntp+1][0], blf[2*ntp+1][1], sBl_u + off);
            }
#pragma unroll
            for (int mt = 0; mt < 4; mt++)
#pragma unroll
                for (int nt = 0; nt < 4; nt++) {
                    mma_bf16(acc[mt][nt], ahf[mt], bhf[nt]);
                    mma_bf16(acc[mt][nt], ahf[mt], blf[nt]);
                    mma_bf16(acc[mt][nt], alf[mt], bhf[nt]);
                }
        }
    }

#pragma unroll
    for (int mt = 0; mt < 4; mt++) {
        int r = m0 + wm * 64 + mt * 16 + (lane >> 2);
#pragma unroll
        for (int nt = 0; nt < 4; nt++) {
            int c = n0 + wn * 32 + nt * 8 + (lane & 3) * 2;
            float2 o0, o1;
            o0.x = (acc[mt][nt][0] + bias[c]) * scale;
            o0.y = (acc[mt][nt][1] + bias[c + 1]) * scale;
            o1.x = (acc[mt][nt][2] + bias[c]) * scale;
            o1.y = (acc[mt][nt][3] + bias[c + 1]) * scale;
            if (EMIT_F32) {
                *(float2*)(Cf + (size_t)r * KD + c) = o0;
                *(float2*)(Cf + (size_t)(r + 8) * KD + c) = o1;
            } else {
                uint32_t h0, l0, h1, l1;
                split2(o0.x, o0.y, h0, l0);
                split2(o1.x, o1.y, h1, l1);
                *(uint32_t*)(Chi + (size_t)r * KD + c) = h0;
                *(uint32_t*)(Clo + (size_t)r * KD + c) = l0;
                *(uint32_t*)(Chi + (size_t)(r + 8) * KD + c) = h1;
                *(uint32_t*)(Clo + (size_t)(r + 8) * KD + c) = l1;
            }
        }
    }
}

// fused QKV projection: grid.z selects which projection
__global__ __launch_bounds__(256, 2) void hgemm_qkv(
    const __nv_bfloat16* __restrict__ Ah, const __nv_bfloat16* __restrict__ Al,
    const float* __restrict__ qb, const float* __restrict__ kb, const float* __restrict__ vb)
{
    __shared__ __align__(16) __nv_bfloat16 sA[2][128 * SSTR];
    __shared__ __align__(16) __nv_bfloat16 sB[2][128 * SSTR];
    int z = blockIdx.z;
    const __nv_bfloat16* Bh = (z == 0) ? g_qwh : (z == 1) ? g_kwh : g_vwh;
    const __nv_bfloat16* Bl = (z == 0) ? g_qwl : (z == 1) ? g_kwl : g_vwl;
    const float* bias       = (z == 0) ? qb    : (z == 1) ? kb    : vb;
    __nv_bfloat16* Chi      = (z == 0) ? g_qh  : (z == 1) ? g_kh  : g_vh;
    __nv_bfloat16* Clo      = (z == 0) ? g_ql  : (z == 1) ? g_kl  : g_vl;
    float scale             = (z == 0) ? 0.125f : 1.0f;
    hgemm_body<false>(Ah, Al, Bh, Bl, bias, nullptr, Chi, Clo, scale,
                      sA[0], sA[1], sB[0], sB[1]);
}

// out-projection: fp32 output
__global__ __launch_bounds__(256, 2) void hgemm_out(
    const __nv_bfloat16* __restrict__ Ah, const __nv_bfloat16* __restrict__ Al,
    const float* __restrict__ bias, float* __restrict__ Cf)
{
    __shared__ __align__(16) __nv_bfloat16 sA[2][128 * SSTR];
    __shared__ __align__(16) __nv_bfloat16 sB[2][128 * SSTR];
    hgemm_body<true>(Ah, Al, g_owh, g_owl, bias, Cf, nullptr, nullptr, 1.0f,
                     sA[0], sA[1], sB[0], sB[1]);
}

// ---------------- HMMA scores: S = Q@K^T (masked) + per-tile stats -----------
#define SC_QH 0
#define SC_QL 9216
#define SC_KH 18432
#define SC_KL 27648
#define SC_SMEM 77824
#define SST 72

__global__ __launch_bounds__(256) void hscores(
    const __nv_bfloat16* __restrict__ qh, const __nv_bfloat16* __restrict__ ql,
    const __nv_bfloat16* __restrict__ kh, const __nv_bfloat16* __restrict__ kl,
    float* __restrict__ W)
{
    extern __shared__ __align__(16) char smraw[];
    __nv_bfloat16* S = (__nv_bfloat16*)smraw;
    float* sMax = (float*)(smraw + 73728);
    float* sSum = (float*)(smraw + 75776);
    uint32_t sb = smem_u32(smraw);

    int bh = blockIdx.z;
    int b = bh >> 4;
    int base = b * EMB + (bh & 15) * HD;
    int n0 = blockIdx.x * 128, m0 = blockIdx.y * 128;
    int tid = threadIdx.x;
    int warp = tid >> 5, lane = tid & 31;
    int wm = warp & 1, wn = warp >> 1;

#pragma unroll
    for (int l = 0; l < 4; l++) {
        int e = tid + 256 * l;
        int row = e >> 3, c8 = (e & 7) * 8;
        size_t qa = (size_t)(m0 + row) * (BSZ*EMB) + base + c8;
        size_t ka = (size_t)(n0 + row) * (BSZ*EMB) + base + c8;
        int so = row * SST + c8;
        *(uint4*)&S[SC_QH + so] = *(const uint4*)(qh + qa);
        *(uint4*)&S[SC_QL + so] = *(const uint4*)(ql + qa);
        *(uint4*)&S[SC_KH + so] = *(const uint4*)(kh + ka);
        *(uint4*)&S[SC_KL + so] = *(const uint4*)(kl + ka);
    }
    __syncthreads();

    float acc[4][4][4];
#pragma unroll
    for (int i = 0; i < 4; i++)
#pragma unroll
        for (int j = 0; j < 4; j++)
#pragma unroll
            for (int q = 0; q < 4; q++) acc[i][j][q] = 0.f;

    int arow = lane & 15;
    int acolh = (lane >> 4) * 8;
    int brow = (lane & 7) + ((lane >> 4) & 1) * 8;
    int bcolh = ((lane >> 3) & 1) * 8;

#pragma unroll
    for (int ks = 0; ks < 64; ks += 16) {
        uint32_t qhf[4][4], qlf[4][4];
#pragma unroll
        for (int mt = 0; mt < 4; mt++) {
            int r = wm * 64 + mt * 16 + arow;
            uint32_t off = sb + (uint32_t)(r * SST + ks + acolh) * 2;
            ldmx4(qhf[mt][0], qhf[mt][1], qhf[mt][2], qhf[mt][3], off + SC_QH * 2);
            ldmx4(qlf[mt][0], qlf[mt][1], qlf[mt][2], qlf[mt][3], off + SC_QL * 2);
        }
        uint32_t khf[4][2], klf[4][2];
#pragma unroll
        for (int ntp = 0; ntp < 2; ntp++) {
            int nb = wn * 32 + ntp * 16;
            uint32_t off = sb + (uint32_t)((nb + brow) * SST + ks + bcolh) * 2;
            ldmx4(khf[2*ntp][0], khf[2*ntp][1], khf[2*ntp+1][0], khf[2*ntp+1][1], off + SC_KH * 2);
            ldmx4(klf[2*ntp][0], klf[2*ntp][1], klf[2*ntp+1][0], klf[2*ntp+1][1], off + SC_KL * 2);
        }
#pragma unroll
        for (int mt = 0; mt < 4; mt++)
#pragma unroll
            for (int nt = 0; nt < 4; nt++) {
                mma_bf16(acc[mt][nt], qhf[mt], khf[nt]);
                mma_bf16(acc[mt][nt], qhf[mt], klf[nt]);
                mma_bf16(acc[mt][nt], qlf[mt], khf[nt]);
            }
    }

    int qr = lane >> 2, qc = (lane & 3) * 2;
    unsigned char mk[4][2];
#pragma unroll
    for (int nt = 0; nt < 4; nt++) {
        int c = n0 + wn * 32 + nt * 8 + qc;
        mk[nt][0] = g_mask[b * TGT + c];
        mk[nt][1] = g_mask[b * TGT + c + 1];
    }
    long long wbase = (long long)bh * TGT * TGT;

#pragma unroll
    for (int mt = 0; mt < 4; mt++) {
        int rl = wm * 64 + mt * 16 + qr;
        int rg = m0 + rl;
        float v0[8], v1[8];
#pragma unroll
        for (int nt = 0; nt < 4; nt++) {
            float x;
            x = acc[mt][nt][0]; if (mk[nt][0]) x = NEGMAX; v0[2*nt]   = x;
            x = acc[mt][nt][1]; if (mk[nt][1]) x = NEGMAX; v0[2*nt+1] = x;
            x = acc[mt][nt][2]; if (mk[nt][0]) x = NEGMAX; v1[2*nt]   = x;
            x = acc[mt][nt][3]; if (mk[nt][1]) x = NEGMAX; v1[2*nt+1] = x;
        }
#pragma unroll
        for (int nt = 0; nt < 4; nt++) {
            int c = n0 + wn * 32 + nt * 8 + qc;
            *(float2*)(W + wbase + (long long)rg * TGT + c) = make_float2(v0[2*nt], v0[2*nt+1]);
            *(float2*)(W + wbase + (long long)(rg + 8) * TGT + c) = make_float2(v1[2*nt], v1[2*nt+1]);
        }
        float mx0 = v0[0], mx1 = v1[0];
#pragma unroll
        for (int j = 1; j < 8; j++) { mx0 = fmaxf(mx0, v0[j]); mx1 = fmaxf(mx1, v1[j]); }
#pragma unroll
        for (int o = 1; o <= 2; o <<= 1) {
            mx0 = fmaxf(mx0, __shfl_xor_sync(0xffffffffu, mx0, o));
            mx1 = fmaxf(mx1, __shfl_xor_sync(0xffffffffu, mx1, o));
        }
        float se0 = 0.f, se1 = 0.f;
#pragma unroll
        for (int j = 0; j < 8; j++) { se0 += __expf(v0[j] - mx0); se1 += __expf(v1[j] - mx1); }
#pragma unroll
        for (int o = 1; o <= 2; o <<= 1) {
            se0 += __shfl_xor_sync(0xffffffffu, se0, o);
            se1 += __shfl_xor_sync(0xffffffffu, se1, o);
        }
        if ((lane & 3) == 0) {
            sMax[rl * 4 + wn] = mx0;       sSum[rl * 4 + wn] = se0;
            sMax[(rl + 8) * 4 + wn] = mx1; sSum[(rl + 8) * 4 + wn] = se1;
        }
    }
    __syncthreads();
    if (tid < 128) {
        float m0v = sMax[tid*4], m1v = sMax[tid*4+1], m2v = sMax[tid*4+2], m3v = sMax[tid*4+3];
        float gm = fmaxf(fmaxf(m0v, m1v), fmaxf(m2v, m3v));
        float s = sSum[tid*4] * __expf(m0v - gm) + sSum[tid*4+1] * __expf(m1v - gm)
                + sSum[tid*4+2] * __expf(m2v - gm) + sSum[tid*4+3] * __expf(m3v - gm);
        int sidx = (bh * NTILE + blockIdx.x) * TGT + m0 + tid;
        g_tmax[sidx] = gm;
        g_tsum[sidx] = s;
    }
}

// ------- combine per-tile stats into per-row (max, 1/sum) ---------------------
__global__ __launch_bounds__(256) void stats_combine()
{
    int idx = blockIdx.x * 256 + threadIdx.x;
    int bh = idx >> 11, row = idx & 2047;
    float gm = -INFINITY;
#pragma unroll
    for (int t = 0; t < NTILE; t++)
        gm = fmaxf(gm, g_tmax[(bh * NTILE + t) * TGT + row]);
    float s = 0.f;
#pragma unroll
    for (int t = 0; t < NTILE; t++)
        s += g_tsum[(bh * NTILE + t) * TGT + row] * __expf(g_tmax[(bh * NTILE + t) * TGT + row] - gm);
    g_rmax[idx] = gm;
    g_rinv[idx] = 1.0f / s;
}

// ---------------- hav2: 64 rows/CTA, 128 threads; S prefetched before V sync --
#define VST 72

__global__ __launch_bounds__(128) void hav2(
    float* __restrict__ W,
    const __nv_bfloat16* __restrict__ vh, const __nv_bfloat16* __restrict__ vl,
    __nv_bfloat16* __restrict__ ch, __nv_bfloat16* __restrict__ cl)
{
    __shared__ __align__(16) __nv_bfloat16 sVh[128 * VST];
    __shared__ __align__(16) __nv_bfloat16 sVl[128 * VST];

    int bh = blockIdx.y, b = bh >> 4;
    int base = b * EMB + (bh & 15) * HD;
    int m0 = blockIdx.x * 64;
    float* P = W + (long long)bh * TGT * TGT;
    int tid = threadIdx.x, wq = tid >> 5, lane = tid & 31;
    int qr = lane >> 2, qc = (lane & 3) * 2;
    int row0 = m0 + wq * 16 + qr;

    float rm0 = g_rmax[bh * TGT + row0],     ri0 = g_rinv[bh * TGT + row0];
    float rm1 = g_rmax[bh * TGT + row0 + 8], ri1 = g_rinv[bh * TGT + row0 + 8];

    uint32_t sVh_u = smem_u32(sVh), sVl_u = smem_u32(sVl);

    float ctx[8][4];
#pragma unroll
    for (int i = 0; i < 8; i++)
#pragma unroll
        for (int q = 0; q < 4; q++) ctx[i][q] = 0.f;

    // V copy geometry: 128 keys x 64 halves; 8 uint4 per thread per array
    int vrow[8], vcol[8];
#pragma unroll
    for (int l = 0; l < 8; l++) { int e = tid + 128 * l; vrow[l] = e >> 3; vcol[l] = (e & 7) * 8; }

    // trans-ldmatrix lane geometry (rows = keys, cols = d)
    int trow = (lane & 7) + ((lane >> 3) & 1) * 8;
    int tcol = ((lane >> 4) & 1) * 8;

    for (int kt = 0; kt < TGT; kt += 128) {
        // ---- issue raw-S loads FIRST (pure gmem->reg; overlaps V copy + syncs)
        float2 p0[16], p1[16];
        long long pr0 = (long long)row0 * TGT + kt + qc;
        long long pr1 = (long long)(row0 + 8) * TGT + kt + qc;
#pragma unroll
        for (int nt = 0; nt < 16; nt++) {
            p0[nt] = *(float2*)(P + pr0 + nt * 8);
            p1[nt] = *(float2*)(P + pr1 + nt * 8);
        }

        __syncthreads();
#pragma unroll
        for (int l = 0; l < 8; l++) {
            size_t ga = (size_t)(kt + vrow[l]) * (BSZ*EMB) + base + vcol[l];
            *(uint4*)&sVh[vrow[l] * VST + vcol[l]] = *(const uint4*)(vh + ga);
            *(uint4*)&sVl[vrow[l] * VST + vcol[l]] = *(const uint4*)(vl + ga);
        }
        __syncthreads();

        // ---- normalize in registers, write P back
#pragma unroll
        for (int nt = 0; nt < 16; nt++) {
            p0[nt].x = __expf(p0[nt].x - rm0) * ri0;
            p0[nt].y = __expf(p0[nt].y - rm0) * ri0;
            p1[nt].x = __expf(p1[nt].x - rm1) * ri1;
            p1[nt].y = __expf(p1[nt].y - rm1) * ri1;
        }
#pragma unroll
        for (int nt = 0; nt < 16; nt++) {
            *(float2*)(P + pr0 + nt * 8) = p0[nt];
            *(float2*)(P + pr1 + nt * 8) = p1[nt];
        }

        // ---- mma: 8 k-chunks of 16 keys; A-frags packed straight from P regs
#pragma unroll
        for (int kc = 0; kc < 8; kc++) {
            uint32_t ah[4], al[4];
            split2(p0[2*kc].x,   p0[2*kc].y,   ah[0], al[0]);
            split2(p1[2*kc].x,   p1[2*kc].y,   ah[1], al[1]);
            split2(p0[2*kc+1].x, p0[2*kc+1].y, ah[2], al[2]);
            split2(p1[2*kc+1].x, p1[2*kc+1].y, ah[3], al[3]);
            int krow = kc * 16 + trow;
#pragma unroll
            for (int ng = 0; ng < 4; ng++) {
                uint32_t off = (uint32_t)(krow * VST + ng * 16 + tcol) * 2;
                uint32_t h0, h1, h2, h3, l0, l1, l2, l3;
                ldmx4t(h0, h1, h2, h3, sVh_u + off);
                ldmx4t(l0, l1, l2, l3, sVl_u + off);
                uint32_t bfh[2]  = {h0, h1}, bfh2[2] = {h2, h3};
                uint32_t bfl[2]  = {l0, l1}, bfl2[2] = {l2, l3};
                mma_bf16(ctx[ng*2], ah, bfh);
                mma_bf16(ctx[ng*2], ah, bfl);
                mma_bf16(ctx[ng*2], al, bfh);
                mma_bf16(ctx[ng*2+1], ah, bfh2);
                mma_bf16(ctx[ng*2+1], ah, bfl2);
                mma_bf16(ctx[ng*2+1], al, bfh2);
            }
        }
    }

    // epilogue: ctx split-bf16 in (t*BSZ+b, h*64+d) layout
#pragma unroll
    for (int nt2 = 0; nt2 < 8; nt2++) {
        int d = nt2 * 8 + qc;
        size_t i0 = (size_t)(row0 * BSZ + b) * EMB + (bh & 15) * HD + d;
        size_t i1 = (size_t)((row0 + 8) * BSZ + b) * EMB + (bh & 15) * HD + d;
        uint32_t h0, l0, h1, l1;
        split2(ctx[nt2][0], ctx[nt2][1], h0, l0);
        split2(ctx[nt2][2], ctx[nt2][3], h1, l1);
        *(uint32_t*)(ch + i0) = h0;
        *(uint32_t*)(cl + i0) = l0;
        *(uint32_t*)(ch + i1) = h1;
        *(uint32_t*)(cl + i1) = l1;
    }
}

// ---------------- mask dtype auto-detect + normalize -------------------------
__global__ void mask_prep(const void* m) {
    __shared__ int mode;
    int tid = threadIdx.x;
    if (tid == 0) {
        const int* mi = (const int*)m;
        int ok_i = 1;
        for (int i = 0; i < 1024; i++) { int v = mi[i]; if (v != 0 && v != 1) { ok_i = 0; break; } }
        if (ok_i) mode = 0;
        else {
            const float* mf = (const float*)m;
            int ok_f = 1;
            for (int i = 0; i < 1024; i++) { float v = mf[i]; if (v != 0.0f && v != 1.0f) { ok_f = 0; break; } }
            mode = ok_f ? 1 : 2;
        }
    }
    __syncthreads();
    int md = mode;
    for (int i = tid; i < BSZ*TGT; i += blockDim.x) {
        bool b;
        if (md == 0)      b = ((const int*)m)[i] != 0;
        else if (md == 1) b = ((const float*)m)[i] != 0.0f;
        else              b = ((const unsigned char*)m)[i] != 0;
        g_mask[i] = b ? 1 : 0;
    }
}

// ---------------- launch -----------------------------------------------------
extern "C" void kernel_launch(void* const* d_in, const int* in_sizes, int n_in,
                              void* d_out, int out_size)
{
    const float* query = (const float*)d_in[0];
    const void*  maskp = d_in[1];
    const float* qw = (const float*)d_in[2];
    const float* qb = (const float*)d_in[3];
    const float* kw = (const float*)d_in[4];
    const float* kb = (const float*)d_in[5];
    const float* vw = (const float*)d_in[6];
    const float* vb = (const float*)d_in[7];
    const float* ow = (const float*)d_in[8];
    const float* ob = (const float*)d_in[9];
    float* out = (float*)d_out;

    float* pwf;
    cudaGetSymbolAddress((void**)&pwf, g_wfallback);

    __nv_bfloat16 *ah, *al, *ch, *cl, *qh_, *ql_, *kh_, *kl_, *vh_, *vl_;
    cudaGetSymbolAddress((void**)&ah,  g_ah);  cudaGetSymbolAddress((void**)&al,  g_al);
    cudaGetSymbolAddress((void**)&ch,  g_ch);  cudaGetSymbolAddress((void**)&cl,  g_cl);
    cudaGetSymbolAddress((void**)&qh_, g_qh);  cudaGetSymbolAddress((void**)&ql_, g_ql);
    cudaGetSymbolAddress((void**)&kh_, g_kh);  cudaGetSymbolAddress((void**)&kl_, g_kl);
    cudaGetSymbolAddress((void**)&vh_, g_vh);  cudaGetSymbolAddress((void**)&vl_, g_vl);

    float* W = ((long long)out_size >= (long long)ATTN_N + W_ELEMS) ? (out + ATTN_N) : pwf;

    cudaFuncSetAttribute(hscores, cudaFuncAttributeMaxDynamicSharedMemorySize, SC_SMEM);

    mask_prep<<<1, 256>>>(maskp);

    split_all<<<(NQ + 4*NW) / 1024, 256>>>(query, qw, kw, vw, ow);

    hgemm_qkv<<<dim3(EMB / 128, ROWS / 128, 3), 256>>>(ah, al, qb, kb, vb);

    hscores<<<dim3(TGT / 128, TGT / 128, BH), 256, SC_SMEM>>>(qh_, ql_, kh_, kl_, W);

    stats_combine<<<BH * TGT / 256, 256>>>();

    hav2<<<dim3(TGT / 64, BH), 128>>>(W, vh_, vl_, ch, cl);

    hgemm_out<<<dim3(EMB / 128, ROWS / 128), 256>>>(ch, cl, ob, out);
}

// round 15
// speedup vs baseline: 1.1685x; 1.1685x over previous
#include <cuda_runtime.h>
#include <cuda_bf16.h>
#include <math.h>
#include <stdint.h>

#define TGT 2048
#define BSZ 2
#define EMB 1024
#define NH 16
#define HD 64
#define ROWS (TGT*BSZ)              // 4096
#define BH (BSZ*NH)                 // 32
#define ATTN_N (ROWS*EMB)           // 4194304
#define W_ELEMS (134217728LL)       // 32*2048*2048
#define NEGMAX (-3.4028234663852886e38f)
#define NTILE 16                    // 2048/128 key tiles
#define KD 1024
#define NQ (ROWS*EMB)               // 4194304
#define NW (EMB*EMB)                // 1048576

// ---------------- scratch (static device memory; no allocations) -------------
__device__ float g_wfallback[134217728];
__device__ unsigned char g_mask[BSZ*TGT];
__device__ float g_tmax[BH*NTILE*TGT];
__device__ float g_tsum[BH*NTILE*TGT];
__device__ float g_rmax[BH*TGT];
__device__ float g_rinv[BH*TGT];

// split-bf16 operands
__device__ __nv_bfloat16 g_ah[ROWS*EMB], g_al[ROWS*EMB];          // input query hi/lo
__device__ __nv_bfloat16 g_ch[ROWS*EMB], g_cl[ROWS*EMB];          // ctx hi/lo
__device__ __nv_bfloat16 g_qh[ROWS*EMB], g_ql[ROWS*EMB];          // projected q hi/lo
__device__ __nv_bfloat16 g_kh[ROWS*EMB], g_kl[ROWS*EMB];          // projected k hi/lo
__device__ __nv_bfloat16 g_vh[ROWS*EMB], g_vl[ROWS*EMB];          // projected v hi/lo
__device__ __nv_bfloat16 g_qwh[EMB*EMB], g_qwl[EMB*EMB];
__device__ __nv_bfloat16 g_kwh[EMB*EMB], g_kwl[EMB*EMB];
__device__ __nv_bfloat16 g_vwh[EMB*EMB], g_vwl[EMB*EMB];
__device__ __nv_bfloat16 g_owh[EMB*EMB], g_owl[EMB*EMB];

// ---------------- helpers ----------------------------------------------------
__device__ __forceinline__ uint32_t smem_u32(const void* p) {
    uint32_t a;
    asm("{ .reg .u64 t; cvta.to.shared.u64 t, %1; cvt.u32.u64 %0, t; }" : "=r"(a) : "l"(p));
    return a;
}
__device__ __forceinline__ void ldmx4(uint32_t& r0, uint32_t& r1, uint32_t& r2, uint32_t& r3, uint32_t addr) {
    asm volatile("ldmatrix.sync.aligned.m8n8.x4.shared.b16 {%0,%1,%2,%3}, [%4];"
                 : "=r"(r0), "=r"(r1), "=r"(r2), "=r"(r3) : "r"(addr));
}
__device__ __forceinline__ void ldmx4t(uint32_t& r0, uint32_t& r1, uint32_t& r2, uint32_t& r3, uint32_t addr) {
    asm volatile("ldmatrix.sync.aligned.m8n8.x4.trans.shared.b16 {%0,%1,%2,%3}, [%4];"
                 : "=r"(r0), "=r"(r1), "=r"(r2), "=r"(r3) : "r"(addr));
}
__device__ __forceinline__ void mma_bf16(float* d, const uint32_t* a, const uint32_t* b) {
    asm volatile("mma.sync.aligned.m16n8k16.row.col.f32.bf16.bf16.f32 "
                 "{%0,%1,%2,%3}, {%4,%5,%6,%7}, {%8,%9}, {%0,%1,%2,%3};"
                 : "+f"(d[0]), "+f"(d[1]), "+f"(d[2]), "+f"(d[3])
                 : "r"(a[0]), "r"(a[1]), "r"(a[2]), "r"(a[3]), "r"(b[0]), "r"(b[1]));
}
__device__ __forceinline__ void split1(float x, __nv_bfloat16& h, __nv_bfloat16& l) {
    h = __float2bfloat16_rn(x);
    l = __float2bfloat16_rn(x - __bfloat162float(h));
}
__device__ __forceinline__ void split2(float x, float y, uint32_t& hi, uint32_t& lo) {
    __nv_bfloat162 h, l;
    split1(x, h.x, l.x);
    split1(y, h.y, l.y);
    hi = *(uint32_t*)&h;
    lo = *(uint32_t*)&l;
}

// ---------------- fused fp32 -> (hi, lo) bf16 split for all 5 tensors --------
__global__ __launch_bounds__(256) void split_all(
    const float* __restrict__ query, const float* __restrict__ qw,
    const float* __restrict__ kw, const float* __restrict__ vw,
    const float* __restrict__ ow)
{
    size_t i = ((size_t)blockIdx.x * 256 + threadIdx.x) * 4;
    const float* src;
    __nv_bfloat16 *hi, *lo;
    size_t off;
    if (i < NQ)              { src = query; hi = g_ah;  lo = g_al;  off = i; }
    else if (i < NQ + NW)    { src = qw;    hi = g_qwh; lo = g_qwl; off = i - NQ; }
    else if (i < NQ + 2*NW)  { src = kw;    hi = g_kwh; lo = g_kwl; off = i - NQ - NW; }
    else if (i < NQ + 3*NW)  { src = vw;    hi = g_vwh; lo = g_vwl; off = i - NQ - 2*NW; }
    else                     { src = ow;    hi = g_owh; lo = g_owl; off = i - NQ - 3*NW; }
    float4 x = *(const float4*)(src + off);
    __nv_bfloat162 hh0, hh1, ll0, ll1;
    split1(x.x, hh0.x, ll0.x); split1(x.y, hh0.y, ll0.y);
    split1(x.z, hh1.x, ll1.x); split1(x.w, hh1.y, ll1.y);
    *(__nv_bfloat162*)(hi + off) = hh0; *(__nv_bfloat162*)(hi + off + 2) = hh1;
    *(__nv_bfloat162*)(lo + off) = ll0; *(__nv_bfloat162*)(lo + off + 2) = ll1;
}

// ---------------- split-bf16 HMMA NT GEMM core --------------------------------
#define SSTR 40

template<bool EMIT_F32>
__device__ __forceinline__ void hgemm_body(
    const __nv_bfloat16* __restrict__ Ah, const __nv_bfloat16* __restrict__ Al,
    const __nv_bfloat16* __restrict__ Bh, const __nv_bfloat16* __restrict__ Bl,
    const float* __restrict__ bias, float* __restrict__ Cf,
    __nv_bfloat16* __restrict__ Chi, __nv_bfloat16* __restrict__ Clo, float scale,
    __nv_bfloat16* sA0, __nv_bfloat16* sA1, __nv_bfloat16* sB0, __nv_bfloat16* sB1)
{
    int tid = threadIdx.x;
    int warp = tid >> 5, lane = tid & 31;
    int wm = warp & 1, wn = warp >> 1;
    int m0 = blockIdx.y * 128, n0 = blockIdx.x * 128;

    uint32_t sAh_u = smem_u32(sA0), sAl_u = smem_u32(sA1);
    uint32_t sBh_u = smem_u32(sB0), sBl_u = smem_u32(sB1);

    float acc[4][4][4];
#pragma unroll
    for (int i = 0; i < 4; i++)
#pragma unroll
        for (int j = 0; j < 4; j++)
#pragma unroll
            for (int q = 0; q < 4; q++) acc[i][j][q] = 0.f;

    int e0 = tid, e1 = tid + 256;
    int r0 = e0 >> 2, c0 = (e0 & 3) * 8;
    int r1 = e1 >> 2, c1 = (e1 & 3) * 8;

    int arow = lane & 15;
    int acolh = (lane >> 4) * 8;
    int brow = (lane & 7) + ((lane >> 4) & 1) * 8;
    int bcolh = ((lane >> 3) & 1) * 8;

    for (int kt = 0; kt < KD; kt += 32) {
        __syncthreads();
        {
            const __nv_bfloat16* a_h = Ah + (size_t)m0 * KD + kt;
            const __nv_bfloat16* a_l = Al + (size_t)m0 * KD + kt;
            const __nv_bfloat16* b_h = Bh + (size_t)n0 * KD + kt;
            const __nv_bfloat16* b_l = Bl + (size_t)n0 * KD + kt;
            *(uint4*)&sA0[r0 * SSTR + c0] = *(const uint4*)(a_h + (size_t)r0 * KD + c0);
            *(uint4*)&sA0[r1 * SSTR + c1] = *(const uint4*)(a_h + (size_t)r1 * KD + c1);
            *(uint4*)&sA1[r0 * SSTR + c0] = *(const uint4*)(a_l + (size_t)r0 * KD + c0);
            *(uint4*)&sA1[r1 * SSTR + c1] = *(const uint4*)(a_l + (size_t)r1 * KD + c1);
            *(uint4*)&sB0[r0 * SSTR + c0] = *(const uint4*)(b_h + (size_t)r0 * KD + c0);
            *(uint4*)&sB0[r1 * SSTR + c1] = *(const uint4*)(b_h + (size_t)r1 * KD + c1);
            *(uint4*)&sB1[r0 * SSTR + c0] = *(const uint4*)(b_l + (size_t)r0 * KD + c0);
            *(uint4*)&sB1[r1 * SSTR + c1] = *(const uint4*)(b_l + (size_t)r1 * KD + c1);
        }
        __syncthreads();

#pragma unroll
        for (int ks = 0; ks < 32; ks += 16) {
            uint32_t ahf[4][4], alf[4][4];
#pragma unroll
            for (int mt = 0; mt < 4; mt++) {
                int r = wm * 64 + mt * 16 + arow;
                uint32_t off = (uint32_t)(r * SSTR + ks + acolh) * 2;
                ldmx4(ahf[mt][0], ahf[mt][1], ahf[mt][2], ahf[mt][3], sAh_u + off);
                ldmx4(alf[mt][0], alf[mt][1], alf[mt][2], alf[mt][3], sAl_u + off);
            }
            uint32_t bhf[4][2], blf[4][2];
#pragma unroll
            for (int ntp = 0; ntp < 2; ntp++) {
                int nb = wn * 32 + ntp * 16;
                uint32_t off = (uint32_t)((nb + brow) * SSTR + ks + bcolh) * 2;
                ldmx4(bhf[2*ntp][0], bhf[2*ntp][1], bhf[2*ntp+1][0], bhf[2*ntp+1][1], sBh_u + off);
                ldmx4(blf[2*ntp][0], blf[2*ntp][1], blf[2*ntp+1][0], blf[2*ntp+1][1], sBl_u + off);
            }
#pragma unroll
            for (int mt = 0; mt < 4; mt++)
#pragma unroll
                for (int nt = 0; nt < 4; nt++) {
                    mma_bf16(acc[mt][nt], ahf[mt], bhf[nt]);
                    mma_bf16(acc[mt][nt], ahf[mt], blf[nt]);
                    mma_bf16(acc[mt][nt], alf[mt], bhf[nt]);
                }
        }
    }

#pragma unroll
    for (int mt = 0; mt < 4; mt++) {
        int r = m0 + wm * 64 + mt * 16 + (lane >> 2);
#pragma unroll
        for (int nt = 0; nt < 4; nt++) {
            int c = n0 + wn * 32 + nt * 8 + (lane & 3) * 2;
            float2 o0, o1;
            o0.x = (acc[mt][nt][0] + bias[c]) * scale;
            o0.y = (acc[mt][nt][1] + bias[c + 1]) * scale;
            o1.x = (acc[mt][nt][2] + bias[c]) * scale;
            o1.y = (acc[mt][nt][3] + bias[c + 1]) * scale;
            if (EMIT_F32) {
                *(float2*)(Cf + (size_t)r * KD + c) = o0;
                *(float2*)(Cf + (size_t)(r + 8) * KD + c) = o1;
            } else {
                uint32_t h0, l0, h1, l1;
                split2(o0.x, o0.y, h0, l0);
                split2(o1.x, o1.y, h1, l1);
                *(uint32_t*)(Chi + (size_t)r * KD + c) = h0;
                *(uint32_t*)(Clo + (size_t)r * KD + c) = l0;
                *(uint32_t*)(Chi + (size_t)(r + 8) * KD + c) = h1;
                *(uint32_t*)(Clo + (size_t)(r + 8) * KD + c) = l1;
            }
        }
    }
}

// fused QKV projection: grid.z selects which projection
__global__ __launch_bounds__(256, 2) void hgemm_qkv(
    const __nv_bfloat16* __restrict__ Ah, const __nv_bfloat16* __restrict__ Al,
    const float* __restrict__ qb, const float* __restrict__ kb, const float* __restrict__ vb)
{
    __shared__ __align__(16) __nv_bfloat16 sA[2][128 * SSTR];
    __shared__ __align__(16) __nv_bfloat16 sB[2][128 * SSTR];
    int z = blockIdx.z;
    const __nv_bfloat16* Bh = (z == 0) ? g_qwh : (z == 1) ? g_kwh : g_vwh;
    const __nv_bfloat16* Bl = (z == 0) ? g_qwl : (z == 1) ? g_kwl : g_vwl;
    const float* bias       = (z == 0) ? qb    : (z == 1) ? kb    : vb;
    __nv_bfloat16* Chi      = (z == 0) ? g_qh  : (z == 1) ? g_kh  : g_vh;
    __nv_bfloat16* Clo      = (z == 0) ? g_ql  : (z == 1) ? g_kl  : g_vl;
    float scale             = (z == 0) ? 0.125f : 1.0f;
    hgemm_body<false>(Ah, Al, Bh, Bl, bias, nullptr, Chi, Clo, scale,
                      sA[0], sA[1], sB[0], sB[1]);
}

// out-projection: fp32 output
__global__ __launch_bounds__(256, 2) void hgemm_out(
    const __nv_bfloat16* __restrict__ Ah, const __nv_bfloat16* __restrict__ Al,
    const float* __restrict__ bias, float* __restrict__ Cf)
{
    __shared__ __align__(16) __nv_bfloat16 sA[2][128 * SSTR];
    __shared__ __align__(16) __nv_bfloat16 sB[2][128 * SSTR];
    hgemm_body<true>(Ah, Al, g_owh, g_owl, bias, Cf, nullptr, nullptr, 1.0f,
                     sA[0], sA[1], sB[0], sB[1]);
}

// ---------------- HMMA scores: S = Q@K^T (masked) + per-tile stats -----------
#define SC_QH 0
#define SC_QL 9216
#define SC_KH 18432
#define SC_KL 27648
#define SC_SMEM 77824
#define SST 72

__global__ __launch_bounds__(256) void hscores(
    const __nv_bfloat16* __restrict__ qh, const __nv_bfloat16* __restrict__ ql,
    const __nv_bfloat16* __restrict__ kh, const __nv_bfloat16* __restrict__ kl,
    float* __restrict__ W)
{
    extern __shared__ __align__(16) char smraw[];
    __nv_bfloat16* S = (__nv_bfloat16*)smraw;
    float* sMax = (float*)(smraw + 73728);
    float* sSum = (float*)(smraw + 75776);
    uint32_t sb = smem_u32(smraw);

    int bh = blockIdx.z;
    int b = bh >> 4;
    int base = b * EMB + (bh & 15) * HD;
    int n0 = blockIdx.x * 128, m0 = blockIdx.y * 128;
    int tid = threadIdx.x;
    int warp = tid >> 5, lane = tid & 31;
    int wm = warp & 1, wn = warp >> 1;

#pragma unroll
    for (int l = 0; l < 4; l++) {
        int e = tid + 256 * l;
        int row = e >> 3, c8 = (e & 7) * 8;
        size_t qa = (size_t)(m0 + row) * (BSZ*EMB) + base + c8;
        size_t ka = (size_t)(n0 + row) * (BSZ*EMB) + base + c8;
        int so = row * SST + c8;
        *(uint4*)&S[SC_QH + so] = *(const uint4*)(qh + qa);
        *(uint4*)&S[SC_QL + so] = *(const uint4*)(ql + qa);
        *(uint4*)&S[SC_KH + so] = *(const uint4*)(kh + ka);
        *(uint4*)&S[SC_KL + so] = *(const uint4*)(kl + ka);
    }
    __syncthreads();

    float acc[4][4][4];
#pragma unroll
    for (int i = 0; i < 4; i++)
#pragma unroll
        for (int j = 0; j < 4; j++)
#pragma unroll
            for (int q = 0; q < 4; q++) acc[i][j][q] = 0.f;

    int arow = lane & 15;
    int acolh = (lane >> 4) * 8;
    int brow = (lane & 7) + ((lane >> 4) & 1) * 8;
    int bcolh = ((lane >> 3) & 1) * 8;

#pragma unroll
    for (int ks = 0; ks < 64; ks += 16) {
        uint32_t qhf[4][4], qlf[4][4];
#pragma unroll
        for (int mt = 0; mt < 4; mt++) {
            int r = wm * 64 + mt * 16 + arow;
            uint32_t off = sb + (uint32_t)(r * SST + ks + acolh) * 2;
            ldmx4(qhf[mt][0], qhf[mt][1], qhf[mt][2], qhf[mt][3], off + SC_QH * 2);
            ldmx4(qlf[mt][0], qlf[mt][1], qlf[mt][2], qlf[mt][3], off + SC_QL * 2);
        }
        uint32_t khf[4][2], klf[4][2];
#pragma unroll
        for (int ntp = 0; ntp < 2; ntp++) {
            int nb = wn * 32 + ntp * 16;
            uint32_t off = sb + (uint32_t)((nb + brow) * SST + ks + bcolh) * 2;
            ldmx4(khf[2*ntp][0], khf[2*ntp][1], khf[2*ntp+1][0], khf[2*ntp+1][1], off + SC_KH * 2);
            ldmx4(klf[2*ntp][0], klf[2*ntp][1], klf[2*ntp+1][0], klf[2*ntp+1][1], off + SC_KL * 2);
        }
#pragma unroll
        for (int mt = 0; mt < 4; mt++)
#pragma unroll
            for (int nt = 0; nt < 4; nt++) {
                mma_bf16(acc[mt][nt], qhf[mt], khf[nt]);
                mma_bf16(acc[mt][nt], qhf[mt], klf[nt]);
                mma_bf16(acc[mt][nt], qlf[mt], khf[nt]);
            }
    }

    int qr = lane >> 2, qc = (lane & 3) * 2;
    unsigned char mk[4][2];
#pragma unroll
    for (int nt = 0; nt < 4; nt++) {
        int c = n0 + wn * 32 + nt * 8 + qc;
        mk[nt][0] = g_mask[b * TGT + c];
        mk[nt][1] = g_mask[b * TGT + c + 1];
    }
    long long wbase = (long long)bh * TGT * TGT;

#pragma unroll
    for (int mt = 0; mt < 4; mt++) {
        int rl = wm * 64 + mt * 16 + qr;
        int rg = m0 + rl;
        float v0[8], v1[8];
#pragma unroll
        for (int nt = 0; nt < 4; nt++) {
            float x;
            x = acc[mt][nt][0]; if (mk[nt][0]) x = NEGMAX; v0[2*nt]   = x;
            x = acc[mt][nt][1]; if (mk[nt][1]) x = NEGMAX; v0[2*nt+1] = x;
            x = acc[mt][nt][2]; if (mk[nt][0]) x = NEGMAX; v1[2*nt]   = x;
            x = acc[mt][nt][3]; if (mk[nt][1]) x = NEGMAX; v1[2*nt+1] = x;
        }
#pragma unroll
        for (int nt = 0; nt < 4; nt++) {
            int c = n0 + wn * 32 + nt * 8 + qc;
            *(float2*)(W + wbase + (long long)rg * TGT + c) = make_float2(v0[2*nt], v0[2*nt+1]);
            *(float2*)(W + wbase + (long long)(rg + 8) * TGT + c) = make_float2(v1[2*nt], v1[2*nt+1]);
        }
        float mx0 = v0[0], mx1 = v1[0];
#pragma unroll
        for (int j = 1; j < 8; j++) { mx0 = fmaxf(mx0, v0[j]); mx1 = fmaxf(mx1, v1[j]); }
#pragma unroll
        for (int o = 1; o <= 2; o <<= 1) {
            mx0 = fmaxf(mx0, __shfl_xor_sync(0xffffffffu, mx0, o));
            mx1 = fmaxf(mx1, __shfl_xor_sync(0xffffffffu, mx1, o));
        }
        float se0 = 0.f, se1 = 0.f;
#pragma unroll
        for (int j = 0; j < 8; j++) { se0 += __expf(v0[j] - mx0); se1 += __expf(v1[j] - mx1); }
#pragma unroll
        for (int o = 1; o <= 2; o <<= 1) {
            se0 += __shfl_xor_sync(0xffffffffu, se0, o);
            se1 += __shfl_xor_sync(0xffffffffu, se1, o);
        }
        if ((lane & 3) == 0) {
            sMax[rl * 4 + wn] = mx0;       sSum[rl * 4 + wn] = se0;
            sMax[(rl + 8) * 4 + wn] = mx1; sSum[(rl + 8) * 4 + wn] = se1;
        }
    }
    __syncthreads();
    if (tid < 128) {
        float m0v = sMax[tid*4], m1v = sMax[tid*4+1], m2v = sMax[tid*4+2], m3v = sMax[tid*4+3];
        float gm = fmaxf(fmaxf(m0v, m1v), fmaxf(m2v, m3v));
        float s = sSum[tid*4] * __expf(m0v - gm) + sSum[tid*4+1] * __expf(m1v - gm)
                + sSum[tid*4+2] * __expf(m2v - gm) + sSum[tid*4+3] * __expf(m3v - gm);
        int sidx = (bh * NTILE + blockIdx.x) * TGT + m0 + tid;
        g_tmax[sidx] = gm;
        g_tsum[sidx] = s;
    }
}

// ------- combine per-tile stats into per-row (max, 1/sum) ---------------------
__global__ __launch_bounds__(256) void stats_combine()
{
    int idx = blockIdx.x * 256 + threadIdx.x;
    int bh = idx >> 11, row = idx & 2047;
    float gm = -INFINITY;
#pragma unroll
    for (int t = 0; t < NTILE; t++)
        gm = fmaxf(gm, g_tmax[(bh * NTILE + t) * TGT + row]);
    float s = 0.f;
#pragma unroll
    for (int t = 0; t < NTILE; t++)
        s += g_tsum[(bh * NTILE + t) * TGT + row] * __expf(g_tmax[(bh * NTILE + t) * TGT + row] - gm);
    g_rmax[idx] = gm;
    g_rinv[idx] = 1.0f / s;
}

// ---------------- hav2: 64 rows/CTA, 128 threads, guaranteed 3 CTAs/SM -------
#define VST 72

__global__ __launch_bounds__(128, 3) void hav2(
    float* __restrict__ W,
    const __nv_bfloat16* __restrict__ vh, const __nv_bfloat16* __restrict__ vl,
    __nv_bfloat16* __restrict__ ch, __nv_bfloat16* __restrict__ cl)
{
    __shared__ __align__(16) __nv_bfloat16 sVh[128 * VST];
    __shared__ __align__(16) __nv_bfloat16 sVl[128 * VST];

    int bh = blockIdx.y, b = bh >> 4;
    int base = b * EMB + (bh & 15) * HD;
    int m0 = blockIdx.x * 64;
    float* P = W + (long long)bh * TGT * TGT;
    int tid = threadIdx.x, wq = tid >> 5, lane = tid & 31;
    int qr = lane >> 2, qc = (lane & 3) * 2;
    int row0 = m0 + wq * 16 + qr;

    float rm0 = g_rmax[bh * TGT + row0],     ri0 = g_rinv[bh * TGT + row0];
    float rm1 = g_rmax[bh * TGT + row0 + 8], ri1 = g_rinv[bh * TGT + row0 + 8];

    uint32_t sVh_u = smem_u32(sVh), sVl_u = smem_u32(sVl);

    float ctx[8][4];
#pragma unroll
    for (int i = 0; i < 8; i++)
#pragma unroll
        for (int q = 0; q < 4; q++) ctx[i][q] = 0.f;

    // V copy geometry: 128 keys x 64 halves; 8 uint4 per thread per array
    int vrow[8], vcol[8];
#pragma unroll
    for (int l = 0; l < 8; l++) { int e = tid + 128 * l; vrow[l] = e >> 3; vcol[l] = (e & 7) * 8; }

    // trans-ldmatrix lane geometry (rows = keys, cols = d)
    int trow = (lane & 7) + ((lane >> 3) & 1) * 8;
    int tcol = ((lane >> 4) & 1) * 8;

    for (int kt = 0; kt < TGT; kt += 128) {
        __syncthreads();
#pragma unroll
        for (int l = 0; l < 8; l++) {
            size_t ga = (size_t)(kt + vrow[l]) * (BSZ*EMB) + base + vcol[l];
            *(uint4*)&sVh[vrow[l] * VST + vcol[l]] = *(const uint4*)(vh + ga);
            *(uint4*)&sVl[vrow[l] * VST + vcol[l]] = *(const uint4*)(vl + ga);
        }
        __syncthreads();

        // load raw S into fragment-position registers, normalize, write P back
        float2 p0[16], p1[16];
        long long pr0 = (long long)row0 * TGT + kt + qc;
        long long pr1 = (long long)(row0 + 8) * TGT + kt + qc;
#pragma unroll
        for (int nt = 0; nt < 16; nt++) {
            float2 s0 = *(float2*)(P + pr0 + nt * 8);
            float2 s1 = *(float2*)(P + pr1 + nt * 8);
            p0[nt].x = __expf(s0.x - rm0) * ri0;
            p0[nt].y = __expf(s0.y - rm0) * ri0;
            p1[nt].x = __expf(s1.x - rm1) * ri1;
            p1[nt].y = __expf(s1.y - rm1) * ri1;
        }
#pragma unroll
        for (int nt = 0; nt < 16; nt++) {
            *(float2*)(P + pr0 + nt * 8) = p0[nt];
            *(float2*)(P + pr1 + nt * 8) = p1[nt];
        }

        // mma: 8 k-chunks of 16 keys; A-frags packed straight from P registers
#pragma unroll
        for (int kc = 0; kc < 8; kc++) {
            uint32_t ah[4], al[4];
            split2(p0[2*kc].x,   p0[2*kc].y,   ah[0], al[0]);
            split2(p1[2*kc].x,   p1[2*kc].y,   ah[1], al[1]);
            split2(p0[2*kc+1].x, p0[2*kc+1].y, ah[2], al[2]);
            split2(p1[2*kc+1].x, p1[2*kc+1].y, ah[3], al[3]);
            int krow = kc * 16 + trow;
#pragma unroll
            for (int ng = 0; ng < 4; ng++) {
                uint32_t off = (uint32_t)(krow * VST + ng * 16 + tcol) * 2;
                uint32_t h0, h1, h2, h3, l0, l1, l2, l3;
                ldmx4t(h0, h1, h2, h3, sVh_u + off);
                ldmx4t(l0, l1, l2, l3, sVl_u + off);
                uint32_t bfh[2]  = {h0, h1}, bfh2[2] = {h2, h3};
                uint32_t bfl[2]  = {l0, l1}, bfl2[2] = {l2, l3};
                mma_bf16(ctx[ng*2], ah, bfh);
                mma_bf16(ctx[ng*2], ah, bfl);
                mma_bf16(ctx[ng*2], al, bfh);
                mma_bf16(ctx[ng*2+1], ah, bfh2);
                mma_bf16(ctx[ng*2+1], ah, bfl2);
                mma_bf16(ctx[ng*2+1], al, bfh2);
            }
        }
    }

    // epilogue: ctx split-bf16 in (t*BSZ+b, h*64+d) layout
#pragma unroll
    for (int nt2 = 0; nt2 < 8; nt2++) {
        int d = nt2 * 8 + qc;
        size_t i0 = (size_t)(row0 * BSZ + b) * EMB + (bh & 15) * HD + d;
        size_t i1 = (size_t)((row0 + 8) * BSZ + b) * EMB + (bh & 15) * HD + d;
        uint32_t h0, l0, h1, l1;
        split2(ctx[nt2][0], ctx[nt2][1], h0, l0);
        split2(ctx[nt2][2], ctx[nt2][3], h1, l1);
        *(uint32_t*)(ch + i0) = h0;
        *(uint32_t*)(cl + i0) = l0;
        *(uint32_t*)(ch + i1) = h1;
        *(uint32_t*)(cl + i1) = l1;
    }
}

// ---------------- mask dtype auto-detect + normalize -------------------------
__global__ void mask_prep(const void* m) {
    __shared__ int mode;
    int tid = threadIdx.x;
    if (tid == 0) {
        const int* mi = (const int*)m;
        int ok_i = 1;
        for (int i = 0; i < 1024; i++) { int v = mi[i]; if (v != 0 && v != 1) { ok_i = 0; break; } }
        if (ok_i) mode = 0;
        else {
            const float* mf = (const float*)m;
            int ok_f = 1;
            for (int i = 0; i < 1024; i++) { float v = mf[i]; if (v != 0.0f && v != 1.0f) { ok_f = 0; break; } }
            mode = ok_f ? 1 : 2;
        }
    }
    __syncthreads();
    int md = mode;
    for (int i = tid; i < BSZ*TGT; i += blockDim.x) {
        bool b;
        if (md == 0)      b = ((const int*)m)[i] != 0;
        else if (md == 1) b = ((const float*)m)[i] != 0.0f;
        else              b = ((const unsigned char*)m)[i] != 0;
        g_mask[i] = b ? 1 : 0;
    }
}

// ---------------- launch -----------------------------------------------------
extern "C" void kernel_launch(void* const* d_in, const int* in_sizes, int n_in,
                              void* d_out, int out_size)
{
    const float* query = (const float*)d_in[0];
    const void*  maskp = d_in[1];
    const float* qw = (const float*)d_in[2];
    const float* qb = (const float*)d_in[3];
    const float* kw = (const float*)d_in[4];
    const float* kb = (const float*)d_in[5];
    const float* vw = (const float*)d_in[6];
    const float* vb = (const float*)d_in[7];
    const float* ow = (const float*)d_in[8];
    const float* ob = (const float*)d_in[9];
    float* out = (float*)d_out;

    float* pwf;
    cudaGetSymbolAddress((void**)&pwf, g_wfallback);

    __nv_bfloat16 *ah, *al, *ch, *cl, *qh_, *ql_, *kh_, *kl_, *vh_, *vl_;
    cudaGetSymbolAddress((void**)&ah,  g_ah);  cudaGetSymbolAddress((void**)&al,  g_al);
    cudaGetSymbolAddress((void**)&ch,  g_ch);  cudaGetSymbolAddress((void**)&cl,  g_cl);
    cudaGetSymbolAddress((void**)&qh_, g_qh);  cudaGetSymbolAddress((void**)&ql_, g_ql);
    cudaGetSymbolAddress((void**)&kh_, g_kh);  cudaGetSymbolAddress((void**)&kl_, g_kl);
    cudaGetSymbolAddress((void**)&vh_, g_vh);  cudaGetSymbolAddress((void**)&vl_, g_vl);

    float* W = ((long long)out_size >= (long long)ATTN_N + W_ELEMS) ? (out + ATTN_N) : pwf;

    cudaFuncSetAttribute(hscores, cudaFuncAttributeMaxDynamicSharedMemorySize, SC_SMEM);

    mask_prep<<<1, 256>>>(maskp);

    split_all<<<(NQ + 4*NW) / 1024, 256>>>(query, qw, kw, vw, ow);

    hgemm_qkv<<<dim3(EMB / 128, ROWS / 128, 3), 256>>>(ah, al, qb, kb, vb);

    hscores<<<dim3(TGT / 128, TGT / 128, BH), 256, SC_SMEM>>>(qh_, ql_, kh_, kl_, W);

    stats_combine<<<BH * TGT / 256, 256>>>();

    hav2<<<dim3(TGT / 64, BH), 128>>>(W, vh_, vl_, ch, cl);

    hgemm_out<<<dim3(EMB / 128, ROWS / 128), 256>>>(ch, cl, ob, out);
}